// round 1
// baseline (speedup 1.0000x reference)
#include <cuda_runtime.h>
#include <math.h>

#define DD 1024
#define HH 16
#define HDIM 64
#define SS 64
#define EE 16
#define BB 32
#define SB 2048   // SS*BB

// ---------------- device scratch (static globals: allocation-free) ----------
__device__ float g_qfull[DD];
__device__ float g_t[HH * DD];
__device__ float g_r[HH * DD];          // r[h][d]
__device__ float g_Wcv[DD * DD];        // Wv_in @ Wv_lin
__device__ float g_bcv[DD];             // Wv_in @ bv_lin + bv_in
__device__ float g_mixed[(size_t)HH * SB * DD];  // [h][sb][d]  (134 MB)
__device__ float g_ctx[(size_t)SB * DD];         // [sb][h*64+j]

// ---------------- generic warp-per-row matvec: y = W x + bias ---------------
__global__ void k_matvec(const float* __restrict__ W, const float* __restrict__ x,
                         const float* __restrict__ bias, float* __restrict__ y) {
    int row  = blockIdx.x * 8 + (threadIdx.x >> 5);
    int lane = threadIdx.x & 31;
    const float* w = W + (size_t)row * DD;
    float acc = 0.f;
    for (int d = lane * 4; d < DD; d += 128) {
        float4 wv = *(const float4*)(w + d);
        float4 xv = *(const float4*)(x + d);
        acc += wv.x * xv.x + wv.y * xv.y + wv.z * xv.z + wv.w * xv.w;
    }
    #pragma unroll
    for (int o = 16; o; o >>= 1) acc += __shfl_xor_sync(0xffffffffu, acc, o);
    if (lane == 0) y[row] = acc + (bias ? bias[row] : 0.f);
}

// t[h][m] = (1/8) * sum_j qfull[h*64+j] * Wk_in[h*64+j, m]
__global__ void k_t_kernel(const float* __restrict__ Wk_in) {
    int idx = blockIdx.x * 256 + threadIdx.x;   // 16384 threads
    int h = idx >> 10, m = idx & 1023;
    const float* q = g_qfull + h * HDIM;
    float acc = 0.f;
    #pragma unroll 8
    for (int j = 0; j < HDIM; j++)
        acc += q[j] * Wk_in[(size_t)(h * HDIM + j) * DD + m];
    g_t[idx] = acc * 0.125f;   // 1/sqrt(hd), hd=64
}

// r[h][d] = sum_m t[h][m] * Wk_lin[m, d]
__global__ void k_r_kernel(const float* __restrict__ Wk_lin) {
    int idx = blockIdx.x * 256 + threadIdx.x;   // 16384 threads
    int h = idx >> 10, d = idx & 1023;
    const float* t = g_t + h * DD;
    float acc = 0.f;
    #pragma unroll 8
    for (int m = 0; m < DD; m++)
        acc += t[m] * Wk_lin[(size_t)m * DD + d];
    g_r[idx] = acc;
}

// ---------------- fused scores + softmax + mixed, one CTA per (s,b) ---------
#define ENT_STRIDE 1028
#define FUSED_SMEM ((16 * ENT_STRIDE + 16 * 16) * 4)

__global__ void __launch_bounds__(256) k_fused(const float* __restrict__ ent,
                                               const unsigned char* __restrict__ pm) {
    extern __shared__ float sm[];
    float* ent_s  = sm;                 // [16][1028]
    float* attn_s = sm + 16 * ENT_STRIDE;  // [16][16]
    int sb = blockIdx.x;
    int s = sb >> 5, b = sb & 31;
    int tid = threadIdx.x;

    // stage entities[s, 0:16, b, :] into smem (16 rows x 1024 floats)
    const float* base = ent + ((size_t)s * EE * BB + b) * DD;
    #pragma unroll
    for (int i = 0; i < 16; i++) {
        int lin = tid + i * 256;            // 4096 float4
        int e = lin >> 8, c = (lin & 255) * 4;
        float4 v = *(const float4*)(base + (size_t)e * BB * DD + c);
        *(float4*)&ent_s[e * ENT_STRIDE + c] = v;
    }
    __syncthreads();

    // scores: thread (h,e) = tid
    int h = tid >> 4, e = tid & 15;
    const float* rr = g_r + h * DD;
    const float* er = ent_s + e * ENT_STRIDE;
    float4 a4 = make_float4(0.f, 0.f, 0.f, 0.f);
    #pragma unroll 4
    for (int c = 0; c < DD; c += 4) {
        float4 rv = __ldg((const float4*)(rr + c));
        float4 ev = *(const float4*)(er + c);
        a4.x += rv.x * ev.x; a4.y += rv.y * ev.y;
        a4.z += rv.z * ev.z; a4.w += rv.w * ev.w;
    }
    float sc = (a4.x + a4.y) + (a4.z + a4.w);
    if (pm[(size_t)(s * EE + e) * BB + b]) sc = -INFINITY;

    // softmax over e (16-lane groups stay within a warp half)
    float mx = sc;
    #pragma unroll
    for (int o = 8; o; o >>= 1) mx = fmaxf(mx, __shfl_xor_sync(0xffffffffu, mx, o));
    float ex = expf(sc - mx);
    float sum = ex;
    #pragma unroll
    for (int o = 8; o; o >>= 1) sum += __shfl_xor_sync(0xffffffffu, sum, o);
    attn_s[h * 16 + e] = ex / sum;
    __syncthreads();

    // mixed[h][sb][d] = sum_e attn[h][e] * ent[e][d]
    int d0 = tid * 4;
    #pragma unroll
    for (int hh = 0; hh < 16; hh++) {
        float4 acc = make_float4(0.f, 0.f, 0.f, 0.f);
        #pragma unroll
        for (int ee = 0; ee < 16; ee++) {
            float w = attn_s[hh * 16 + ee];
            float4 ev = *(const float4*)&ent_s[ee * ENT_STRIDE + d0];
            acc.x += w * ev.x; acc.y += w * ev.y;
            acc.z += w * ev.z; acc.w += w * ev.w;
        }
        *(float4*)&g_mixed[((size_t)hh * SB + sb) * DD + d0] = acc;
    }
}

// ---------------- tiled fp32 GEMM: C = A * B(^T) + bias, batched over z -----
// BT=true : B is [N,K] row-major (C[m,n] = sum_k A[m,k]*B[n,k])
// BT=false: B is [K,N] row-major (C[m,n] = sum_k A[m,k]*B[k,n])
template <bool BT>
__global__ void __launch_bounds__(128) gemm128x64(
    const float* __restrict__ A, const float* __restrict__ Bm,
    const float* __restrict__ bias, float* __restrict__ C,
    int K, int lda, int ldb, int ldc,
    long long sA, long long sB, long long sBias, long long sC) {
    constexpr int BM = 128, BN = 64, BK = 32;
    __shared__ float As[BK][BM + 4];
    __shared__ float Bs[BK][BN + 4];
    int m0 = blockIdx.y * BM;
    int n0 = blockIdx.x * BN;
    long long z = blockIdx.z;
    A  += z * sA;
    Bm += z * sB;
    C  += z * sC;
    const float* bi = bias ? (bias + z * sBias) : nullptr;

    int tid = threadIdx.x;
    int tx = tid & 7, ty = tid >> 3;
    float acc[8][8] = {};

    for (int kt = 0; kt < K; kt += BK) {
        #pragma unroll
        for (int i = 0; i < 8; i++) {        // A tile: 128x32 = 1024 float4
            int lin = tid + i * 128;
            int m = lin >> 3, k4 = (lin & 7) * 4;
            float4 v = *(const float4*)(A + (long long)(m0 + m) * lda + kt + k4);
            As[k4 + 0][m] = v.x; As[k4 + 1][m] = v.y;
            As[k4 + 2][m] = v.z; As[k4 + 3][m] = v.w;
        }
        if (BT) {
            #pragma unroll
            for (int i = 0; i < 4; i++) {    // B tile: 64x32
                int lin = tid + i * 128;
                int n = lin >> 3, k4 = (lin & 7) * 4;
                float4 v = *(const float4*)(Bm + (long long)(n0 + n) * ldb + kt + k4);
                Bs[k4 + 0][n] = v.x; Bs[k4 + 1][n] = v.y;
                Bs[k4 + 2][n] = v.z; Bs[k4 + 3][n] = v.w;
            }
        } else {
            #pragma unroll
            for (int i = 0; i < 4; i++) {    // B tile: 32x64
                int lin = tid + i * 128;
                int k = lin >> 4, n4 = (lin & 15) * 4;
                float4 v = *(const float4*)(Bm + (long long)(kt + k) * ldb + n0 + n4);
                *(float4*)&Bs[k][n4] = v;
            }
        }
        __syncthreads();
        #pragma unroll
        for (int kk = 0; kk < BK; kk++) {
            float a[8], bvals[8];
            *(float4*)&a[0] = *(const float4*)&As[kk][ty * 8 + 0];
            *(float4*)&a[4] = *(const float4*)&As[kk][ty * 8 + 4];
            *(float4*)&bvals[0] = *(const float4*)&Bs[kk][tx * 8 + 0];
            *(float4*)&bvals[4] = *(const float4*)&Bs[kk][tx * 8 + 4];
            #pragma unroll
            for (int i = 0; i < 8; i++)
                #pragma unroll
                for (int j = 0; j < 8; j++)
                    acc[i][j] += a[i] * bvals[j];
        }
        __syncthreads();
    }

    #pragma unroll
    for (int i = 0; i < 8; i++) {
        int m = m0 + ty * 8 + i;
        #pragma unroll
        for (int j = 0; j < 8; j += 4) {
            int n = n0 + tx * 8 + j;
            float4 v;
            v.x = acc[i][j + 0] + (bi ? bi[n + 0] : 0.f);
            v.y = acc[i][j + 1] + (bi ? bi[n + 1] : 0.f);
            v.z = acc[i][j + 2] + (bi ? bi[n + 2] : 0.f);
            v.w = acc[i][j + 3] + (bi ? bi[n + 3] : 0.f);
            *(float4*)(C + (long long)m * ldc + n) = v;
        }
    }
}

// ---------------- launch ----------------------------------------------------
extern "C" void kernel_launch(void* const* d_in, const int* in_sizes, int n_in,
                              void* d_out, int out_size) {
    const float*         entities = (const float*)d_in[0];
    const unsigned char* pm       = (const unsigned char*)d_in[1];
    // d_in[2] = n_sents (compile-time 64)
    const float* query  = (const float*)d_in[3];
    const float* Wk_lin = (const float*)d_in[4];
    // d_in[5] = bk_lin: cancels in softmax (constant over e) -> unused
    const float* Wv_lin = (const float*)d_in[6];
    const float* bv_lin = (const float*)d_in[7];
    const float* Wq_in  = (const float*)d_in[8];
    const float* bq_in  = (const float*)d_in[9];
    const float* Wk_in  = (const float*)d_in[10];
    // d_in[11] = bk_in: cancels in softmax -> unused
    const float* Wv_in  = (const float*)d_in[12];
    const float* bv_in  = (const float*)d_in[13];
    const float* Wo     = (const float*)d_in[14];
    const float* bo     = (const float*)d_in[15];
    float* out = (float*)d_out;

    float *gq, *gWcv, *gbcv, *gmixed, *gctx;
    cudaGetSymbolAddress((void**)&gq,     g_qfull);
    cudaGetSymbolAddress((void**)&gWcv,   g_Wcv);
    cudaGetSymbolAddress((void**)&gbcv,   g_bcv);
    cudaGetSymbolAddress((void**)&gmixed, g_mixed);
    cudaGetSymbolAddress((void**)&gctx,   g_ctx);

    // q_full = Wq_in @ query + bq_in
    k_matvec<<<128, 256>>>(Wq_in, query, bq_in, gq);
    // t[h] = (q_h/8) @ Wk_in[h-slice] ; r[h] = t[h] @ Wk_lin
    k_t_kernel<<<64, 256>>>(Wk_in);
    k_r_kernel<<<64, 256>>>(Wk_lin);
    // bcv = Wv_in @ bv_lin + bv_in
    k_matvec<<<128, 256>>>(Wv_in, bv_lin, bv_in, gbcv);
    // Wcv = Wv_in @ Wv_lin   (NN GEMM, 1024^3)
    gemm128x64<false><<<dim3(16, 8, 1), 128>>>(
        Wv_in, Wv_lin, nullptr, gWcv, DD, DD, DD, DD, 0, 0, 0, 0);

    // fused scores + softmax + mixed
    cudaFuncSetAttribute(k_fused, cudaFuncAttributeMaxDynamicSharedMemorySize, FUSED_SMEM);
    k_fused<<<SB, 256, FUSED_SMEM>>>(entities, pm);

    // ctx_h = mixed_h @ Wcv_h^T + bcv_h   (16 batched NT GEMMs [2048x1024]x[64x1024]^T)
    gemm128x64<true><<<dim3(1, 16, HH), 128>>>(
        gmixed, gWcv, gbcv, gctx, DD, DD, DD, DD,
        (long long)SB * DD, (long long)HDIM * DD, HDIM, HDIM);

    // out = ctx @ Wo^T + bo   (NT GEMM [2048x1024]x[1024x1024]^T)
    gemm128x64<true><<<dim3(16, 16, 1), 128>>>(
        gctx, Wo, bo, out, DD, DD, DD, DD, 0, 0, 0, 0);
}

// round 3
// speedup vs baseline: 1.2023x; 1.2023x over previous
#include <cuda_runtime.h>
#include <math.h>
#include <stdint.h>

#define DD 1024
#define HH 16
#define HDIM 64
#define SS 64
#define EE 16
#define BB 32
#define SB 2048   // SS*BB

// ---------------- device scratch ----------------
__device__ float g_qfull[DD];
__device__ float g_t[HH * DD];
__device__ float g_r[HH * DD];
__device__ float g_WvlinT[DD * DD];
__device__ float g_Wcv[DD * DD];
__device__ float g_bcv[DD];
__device__ float g_mixed[(size_t)HH * SB * DD];
__device__ float g_ctx[(size_t)SB * DD];

// ---------------- helpers ----------------
__device__ __forceinline__ uint32_t f2tf32(float x) {
    uint32_t y; asm("cvt.rna.tf32.f32 %0, %1;" : "=r"(y) : "f"(x)); return y;
}
__device__ __forceinline__ void mma_tf32(float* d, const uint32_t* a, const uint32_t* b) {
    asm volatile("mma.sync.aligned.m16n8k8.row.col.f32.tf32.tf32.f32 "
        "{%0,%1,%2,%3}, {%4,%5,%6,%7}, {%8,%9}, {%0,%1,%2,%3};"
        : "+f"(d[0]), "+f"(d[1]), "+f"(d[2]), "+f"(d[3])
        : "r"(a[0]), "r"(a[1]), "r"(a[2]), "r"(a[3]), "r"(b[0]), "r"(b[1]));
}

// ======== tf32 mma.sync NT GEMM: C[m,n] = sum_k A[m,k]*B[n,k] + bias ========
// BM=128, BK=32. 8 warps in a WM x WN grid; warp tile = (MT*16) x (NT*8).
template <int BN, int WM, int WN, int MT, int NT>
__global__ void __launch_bounds__(256) gemm_mma(
    const float* __restrict__ Ag, const float* __restrict__ Bg,
    const float* __restrict__ biasg, float* __restrict__ Cg,
    int lda, int ldb, int ldc, int K,
    long long aZ, long long bZ, long long biasZ, long long cZ)
{
    constexpr int BM = 128;
    constexpr int SA_KG = BM * 8 + 4;   // floats per k-group slab (+pad)
    constexpr int SB_KG = BN * 8 + 4;
    constexpr int NUA = (BM * 4) / 256; // (m,kg) units per thread for A
    constexpr int NUB = (BN * 4) / 256;

    __shared__ __align__(16) uint32_t As[4 * SA_KG];
    __shared__ __align__(16) uint32_t Bs[4 * SB_KG];

    const int tid = threadIdx.x;
    const int wid = tid >> 5, lane = tid & 31;
    const int g = lane >> 2, c = lane & 3;
    const int wm = wid % WM, wn = wid / WM;
    const int m_base = wm * (MT * 16);
    const int n_base = wn * (NT * 8);

    const float* A = Ag + (long long)blockIdx.z * aZ;
    const float* B = Bg + (long long)blockIdx.z * bZ;
    float* C = Cg + (long long)blockIdx.z * cZ;
    const float* bias = biasg ? (biasg + (long long)blockIdx.z * biasZ) : (const float*)0;
    const int m0 = blockIdx.y * BM;
    const int n0 = blockIdx.x * BN;

    // per-thread load units: u -> (m = u>>2, kg = u&3), 8 consecutive k floats
    const float* pA[NUA]; uint32_t stA[NUA];
    #pragma unroll
    for (int i = 0; i < NUA; i++) {
        int u = tid + i * 256; int m = u >> 2, kg = u & 3;
        pA[i] = A + (size_t)(m0 + m) * lda + kg * 8;
        stA[i] = kg * SA_KG + m * 8;
    }
    const float* pB[NUB]; uint32_t stB[NUB];
    #pragma unroll
    for (int i = 0; i < NUB; i++) {
        int u = tid + i * 256; int n = u >> 2, kg = u & 3;
        pB[i] = B + (size_t)(n0 + n) * ldb + kg * 8;
        stB[i] = kg * SB_KG + n * 8;
    }

    float acc[MT][NT][4];
    #pragma unroll
    for (int i = 0; i < MT; i++)
        #pragma unroll
        for (int j = 0; j < NT; j++)
            #pragma unroll
            for (int q = 0; q < 4; q++) acc[i][j][q] = 0.f;

    const int NTILES = K >> 5;
    float4 ra[NUA][2], rb[NUB][2];
    #pragma unroll
    for (int i = 0; i < NUA; i++) {
        ra[i][0] = *(const float4*)(pA[i]);
        ra[i][1] = *(const float4*)(pA[i] + 4);
    }
    #pragma unroll
    for (int i = 0; i < NUB; i++) {
        rb[i][0] = *(const float4*)(pB[i]);
        rb[i][1] = *(const float4*)(pB[i] + 4);
    }

    for (int kt = 0; kt < NTILES; kt++) {
        __syncthreads();   // previous tile's compute done
        #pragma unroll
        for (int i = 0; i < NUA; i++) {
            uint4 u0 = make_uint4(f2tf32(ra[i][0].x), f2tf32(ra[i][0].y),
                                  f2tf32(ra[i][0].z), f2tf32(ra[i][0].w));
            uint4 u1 = make_uint4(f2tf32(ra[i][1].x), f2tf32(ra[i][1].y),
                                  f2tf32(ra[i][1].z), f2tf32(ra[i][1].w));
            *(uint4*)&As[stA[i]] = u0;
            *(uint4*)&As[stA[i] + 4] = u1;
        }
        #pragma unroll
        for (int i = 0; i < NUB; i++) {
            uint4 u0 = make_uint4(f2tf32(rb[i][0].x), f2tf32(rb[i][0].y),
                                  f2tf32(rb[i][0].z), f2tf32(rb[i][0].w));
            uint4 u1 = make_uint4(f2tf32(rb[i][1].x), f2tf32(rb[i][1].y),
                                  f2tf32(rb[i][1].z), f2tf32(rb[i][1].w));
            *(uint4*)&Bs[stB[i]] = u0;
            *(uint4*)&Bs[stB[i] + 4] = u1;
        }
        if (kt + 1 < NTILES) {
            #pragma unroll
            for (int i = 0; i < NUA; i++) {
                ra[i][0] = *(const float4*)(pA[i] + (kt + 1) * 32);
                ra[i][1] = *(const float4*)(pA[i] + (kt + 1) * 32 + 4);
            }
            #pragma unroll
            for (int i = 0; i < NUB; i++) {
                rb[i][0] = *(const float4*)(pB[i] + (kt + 1) * 32);
                rb[i][1] = *(const float4*)(pB[i] + (kt + 1) * 32 + 4);
            }
        }
        __syncthreads();

        #pragma unroll
        for (int kg = 0; kg < 4; kg++) {
            uint32_t af[MT][4];
            #pragma unroll
            for (int mt = 0; mt < MT; mt++) {
                int r0 = kg * SA_KG + (m_base + mt * 16 + g) * 8 + c;
                af[mt][0] = As[r0];      // (g,   c)
                af[mt][1] = As[r0 + 64]; // (g+8, c)
                af[mt][2] = As[r0 + 4];  // (g,   c+4)
                af[mt][3] = As[r0 + 68]; // (g+8, c+4)
            }
            uint32_t bf[NT][2];
            #pragma unroll
            for (int nt = 0; nt < NT; nt++) {
                int q = kg * SB_KG + (n_base + nt * 8 + g) * 8 + c;
                bf[nt][0] = Bs[q];
                bf[nt][1] = Bs[q + 4];
            }
            #pragma unroll
            for (int mt = 0; mt < MT; mt++)
                #pragma unroll
                for (int nt = 0; nt < NT; nt++)
                    mma_tf32(acc[mt][nt], af[mt], bf[nt]);
        }
    }

    // epilogue
    #pragma unroll
    for (int mt = 0; mt < MT; mt++) {
        int row = m0 + m_base + mt * 16 + g;
        #pragma unroll
        for (int nt = 0; nt < NT; nt++) {
            int col = n0 + n_base + nt * 8 + 2 * c;
            float bx = 0.f, by = 0.f;
            if (bias) { bx = bias[col]; by = bias[col + 1]; }
            float2 v0 = make_float2(acc[mt][nt][0] + bx, acc[mt][nt][1] + by);
            float2 v1 = make_float2(acc[mt][nt][2] + bx, acc[mt][nt][3] + by);
            *(float2*)(C + (size_t)row * ldc + col) = v0;
            *(float2*)(C + (size_t)(row + 8) * ldc + col) = v1;
        }
    }
}

// ================= small prep kernels =================
__global__ void k_matvec(const float* __restrict__ W, const float* __restrict__ x,
                         const float* __restrict__ bias, float* __restrict__ y) {
    int row = blockIdx.x * 8 + (threadIdx.x >> 5);
    int lane = threadIdx.x & 31;
    const float* w = W + (size_t)row * DD;
    float acc = 0.f;
    for (int d = lane * 4; d < DD; d += 128) {
        float4 wv = *(const float4*)(w + d);
        float4 xv = *(const float4*)(x + d);
        acc += wv.x * xv.x + wv.y * xv.y + wv.z * xv.z + wv.w * xv.w;
    }
    #pragma unroll
    for (int o = 16; o; o >>= 1) acc += __shfl_xor_sync(0xffffffffu, acc, o);
    if (lane == 0) y[row] = acc + (bias ? bias[row] : 0.f);
}

__global__ void k_t_kernel(const float* __restrict__ Wk_in) {
    int idx = blockIdx.x * 256 + threadIdx.x;
    int h = idx >> 10, m = idx & 1023;
    const float* q = g_qfull + h * HDIM;
    float acc = 0.f;
    #pragma unroll 8
    for (int j = 0; j < HDIM; j++)
        acc += q[j] * Wk_in[(size_t)(h * HDIM + j) * DD + m];
    g_t[idx] = acc * 0.125f;
}

__global__ void k_r_kernel(const float* __restrict__ Wk_lin) {
    int idx = blockIdx.x * 256 + threadIdx.x;
    int h = idx >> 10, d = idx & 1023;
    const float* t = g_t + h * DD;
    float acc = 0.f;
    #pragma unroll 8
    for (int m = 0; m < DD; m++)
        acc += t[m] * Wk_lin[(size_t)m * DD + d];
    g_r[idx] = acc;
}

__global__ void k_transpose(const float* __restrict__ in, float* __restrict__ out) {
    __shared__ float t[32][33];
    int x = blockIdx.x * 32 + threadIdx.x;
    int y = blockIdx.y * 32 + threadIdx.y;
    #pragma unroll
    for (int j = 0; j < 32; j += 8)
        t[threadIdx.y + j][threadIdx.x] = in[(size_t)(y + j) * DD + x];
    __syncthreads();
    x = blockIdx.y * 32 + threadIdx.x;
    y = blockIdx.x * 32 + threadIdx.y;
    #pragma unroll
    for (int j = 0; j < 32; j += 8)
        out[(size_t)(y + j) * DD + x] = t[threadIdx.x][threadIdx.y + j];
}

// ============ fused scores + softmax + mixed, one CTA per (s,b) =============
#define ENT_STRIDE 1028
#define FUSED_SMEM ((16 * ENT_STRIDE + 512 + 256) * 4)

__global__ void __launch_bounds__(256) k_fused(const float* __restrict__ ent,
                                               const unsigned char* __restrict__ pm) {
    extern __shared__ float sm[];
    float* ent_s  = sm;                       // [16][1028]
    float* part_s = sm + 16 * ENT_STRIDE;     // [2][16][16]
    float* attn_t = part_s + 512;             // [e][h]
    int sb = blockIdx.x;
    int s = sb >> 5, b = sb & 31;
    int tid = threadIdx.x;

    const float* base = ent + ((size_t)s * EE * BB + b) * DD;
    #pragma unroll
    for (int i = 0; i < 16; i++) {
        int lin = tid + i * 256;
        int e = lin >> 8, cc = (lin & 255) * 4;
        float4 v = *(const float4*)(base + (size_t)e * BB * DD + cc);
        *(float4*)&ent_s[e * ENT_STRIDE + cc] = v;
    }
    __syncthreads();

    {
        int e = tid & 15, h2 = (tid >> 4) & 7, half = tid >> 7;
        int h0 = h2 * 2;
        const float* r0 = g_r + (size_t)h0 * DD + half * 512;
        const float* r1 = r0 + DD;
        const float* ev = ent_s + e * ENT_STRIDE + half * 512;
        float s0 = 0.f, s1 = 0.f;
        #pragma unroll 8
        for (int i = 0; i < 512; i += 4) {
            float4 eV = *(const float4*)(ev + i);
            float4 rA = __ldg((const float4*)(r0 + i));
            float4 rB = __ldg((const float4*)(r1 + i));
            s0 += rA.x * eV.x + rA.y * eV.y + rA.z * eV.z + rA.w * eV.w;
            s1 += rB.x * eV.x + rB.y * eV.y + rB.z * eV.z + rB.w * eV.w;
        }
        part_s[half * 256 + h0 * 16 + e] = s0;
        part_s[half * 256 + (h0 + 1) * 16 + e] = s1;
    }
    __syncthreads();

    {
        int h = tid >> 4, e = tid & 15;
        float sc = part_s[h * 16 + e] + part_s[256 + h * 16 + e];
        if (pm[(size_t)(s * EE + e) * BB + b]) sc = -INFINITY;
        float mx = sc;
        #pragma unroll
        for (int o = 8; o; o >>= 1) mx = fmaxf(mx, __shfl_xor_sync(0xffffffffu, mx, o));
        float ex = expf(sc - mx);
        float sum = ex;
        #pragma unroll
        for (int o = 8; o; o >>= 1) sum += __shfl_xor_sync(0xffffffffu, sum, o);
        attn_t[e * 16 + h] = ex / sum;
    }
    __syncthreads();

    {
        int d0 = tid * 4;
        float4 acc[16];
        #pragma unroll
        for (int h = 0; h < 16; h++) acc[h] = make_float4(0.f, 0.f, 0.f, 0.f);
        #pragma unroll
        for (int e = 0; e < 16; e++) {
            float4 v = *(const float4*)&ent_s[e * ENT_STRIDE + d0];
            float4 w0 = *(const float4*)&attn_t[e * 16 + 0];
            float4 w1 = *(const float4*)&attn_t[e * 16 + 4];
            float4 w2 = *(const float4*)&attn_t[e * 16 + 8];
            float4 w3 = *(const float4*)&attn_t[e * 16 + 12];
            acc[0].x += w0.x * v.x;  acc[0].y += w0.x * v.y;  acc[0].z += w0.x * v.z;  acc[0].w += w0.x * v.w;
            acc[1].x += w0.y * v.x;  acc[1].y += w0.y * v.y;  acc[1].z += w0.y * v.z;  acc[1].w += w0.y * v.w;
            acc[2].x += w0.z * v.x;  acc[2].y += w0.z * v.y;  acc[2].z += w0.z * v.z;  acc[2].w += w0.z * v.w;
            acc[3].x += w0.w * v.x;  acc[3].y += w0.w * v.y;  acc[3].z += w0.w * v.z;  acc[3].w += w0.w * v.w;
            acc[4].x += w1.x * v.x;  acc[4].y += w1.x * v.y;  acc[4].z += w1.x * v.z;  acc[4].w += w1.x * v.w;
            acc[5].x += w1.y * v.x;  acc[5].y += w1.y * v.y;  acc[5].z += w1.y * v.z;  acc[5].w += w1.y * v.w;
            acc[6].x += w1.z * v.x;  acc[6].y += w1.z * v.y;  acc[6].z += w1.z * v.z;  acc[6].w += w1.z * v.w;
            acc[7].x += w1.w * v.x;  acc[7].y += w1.w * v.y;  acc[7].z += w1.w * v.z;  acc[7].w += w1.w * v.w;
            acc[8].x += w2.x * v.x;  acc[8].y += w2.x * v.y;  acc[8].z += w2.x * v.z;  acc[8].w += w2.x * v.w;
            acc[9].x += w2.y * v.x;  acc[9].y += w2.y * v.y;  acc[9].z += w2.y * v.z;  acc[9].w += w2.y * v.w;
            acc[10].x += w2.z * v.x; acc[10].y += w2.z * v.y; acc[10].z += w2.z * v.z; acc[10].w += w2.z * v.w;
            acc[11].x += w2.w * v.x; acc[11].y += w2.w * v.y; acc[11].z += w2.w * v.z; acc[11].w += w2.w * v.w;
            acc[12].x += w3.x * v.x; acc[12].y += w3.x * v.y; acc[12].z += w3.x * v.z; acc[12].w += w3.x * v.w;
            acc[13].x += w3.y * v.x; acc[13].y += w3.y * v.y; acc[13].z += w3.y * v.z; acc[13].w += w3.y * v.w;
            acc[14].x += w3.z * v.x; acc[14].y += w3.z * v.y; acc[14].z += w3.z * v.z; acc[14].w += w3.z * v.w;
            acc[15].x += w3.w * v.x; acc[15].y += w3.w * v.y; acc[15].z += w3.w * v.z; acc[15].w += w3.w * v.w;
        }
        #pragma unroll
        for (int h = 0; h < 16; h++)
            *(float4*)&g_mixed[((size_t)h * SB + sb) * DD + d0] = acc[h];
    }
}

// ================= launch =================
extern "C" void kernel_launch(void* const* d_in, const int* in_sizes, int n_in,
                              void* d_out, int out_size) {
    const float*         entities = (const float*)d_in[0];
    const unsigned char* pm       = (const unsigned char*)d_in[1];
    const float* query  = (const float*)d_in[3];
    const float* Wk_lin = (const float*)d_in[4];
    const float* Wv_lin = (const float*)d_in[6];
    const float* bv_lin = (const float*)d_in[7];
    const float* Wq_in  = (const float*)d_in[8];
    const float* bq_in  = (const float*)d_in[9];
    const float* Wk_in  = (const float*)d_in[10];
    const float* Wv_in  = (const float*)d_in[12];
    const float* bv_in  = (const float*)d_in[13];
    const float* Wo     = (const float*)d_in[14];
    const float* bo     = (const float*)d_in[15];
    float* out = (float*)d_out;

    float *gq, *gWvT, *gWcv, *gbcv, *gmixed, *gctx;
    cudaGetSymbolAddress((void**)&gq,     g_qfull);
    cudaGetSymbolAddress((void**)&gWvT,   g_WvlinT);
    cudaGetSymbolAddress((void**)&gWcv,   g_Wcv);
    cudaGetSymbolAddress((void**)&gbcv,   g_bcv);
    cudaGetSymbolAddress((void**)&gmixed, g_mixed);
    cudaGetSymbolAddress((void**)&gctx,   g_ctx);

    cudaFuncSetAttribute(k_fused, cudaFuncAttributeMaxDynamicSharedMemorySize, FUSED_SMEM);

    // scalar/query preprocessing (fp32)
    k_matvec<<<128, 256>>>(Wq_in, query, bq_in, gq);
    k_t_kernel<<<64, 256>>>(Wk_in);
    k_r_kernel<<<64, 256>>>(Wk_lin);
    k_matvec<<<128, 256>>>(Wv_in, bv_lin, bv_in, gbcv);
    k_transpose<<<dim3(32, 32), dim3(32, 8)>>>(Wv_lin, gWvT);

    // Wcv = Wv_in @ Wv_lin  ==>  NT: A=Wv_in, B=Wv_lin^T
    gemm_mma<128, 2, 4, 4, 4><<<dim3(8, 8, 1), 256>>>(
        Wv_in, gWvT, nullptr, gWcv, DD, DD, DD, DD, 0, 0, 0, 0);

    // fused scores + softmax + mixed
    k_fused<<<SB, 256, FUSED_SMEM>>>(entities, pm);

    // ctx_h = mixed_h @ Wcv_h^T + bcv_h  (z = head)
    gemm_mma<64, 4, 2, 2, 4><<<dim3(1, 16, HH), 256>>>(
        gmixed, gWcv, gbcv, gctx, DD, DD, DD, DD,
        (long long)SB * DD, (long long)HDIM * DD, HDIM, HDIM);

    // out = ctx @ Wo^T + bo
    gemm_mma<128, 2, 4, 4, 4><<<dim3(8, 16, 1), 256>>>(
        gctx, Wo, bo, out, DD, DD, DD, DD, 0, 0, 0, 0);
}

// round 4
// speedup vs baseline: 2.0453x; 1.7012x over previous
#include <cuda_runtime.h>
#include <cuda_fp16.h>
#include <math.h>
#include <stdint.h>

#define DD 1024
#define HH 16
#define HDIM 64
#define SS 64
#define EE 16
#define BB 32
#define SB 2048   // SS*BB

// ---------------- device scratch ----------------
__device__ float g_qfull[DD];
__device__ float g_t[HH * DD];
__device__ float g_r[HH * DD];
__device__ float g_bcv[DD];
__device__ __align__(16) __half g_Wvin16[DD * DD];
__device__ __align__(16) __half g_WvlinT16[DD * DD];
__device__ __align__(16) __half g_Wo16[DD * DD];
__device__ __align__(16) __half g_Wcv16[DD * DD];
__device__ __align__(16) __half g_mixed16[(size_t)HH * SB * DD];
__device__ __align__(16) __half g_ctx16[(size_t)SB * DD];

// ---------------- PTX helpers ----------------
__device__ __forceinline__ uint32_t smem_u32(const void* p) {
    uint32_t a;
    asm("{ .reg .u64 t; cvta.to.shared.u64 t, %1; cvt.u32.u64 %0, t; }" : "=r"(a) : "l"(p));
    return a;
}
__device__ __forceinline__ void cp_async16(uint32_t saddr, const void* gaddr) {
    asm volatile("cp.async.cg.shared.global [%0], [%1], 16;" :: "r"(saddr), "l"(gaddr));
}
#define CP_COMMIT() asm volatile("cp.async.commit_group;" ::: "memory")
#define CP_WAIT2()  asm volatile("cp.async.wait_group 2;" ::: "memory")

__device__ __forceinline__ void ldm4(uint32_t& r0, uint32_t& r1, uint32_t& r2, uint32_t& r3,
                                     uint32_t addr) {
    asm volatile("ldmatrix.sync.aligned.m8n8.x4.shared.b16 {%0,%1,%2,%3}, [%4];"
        : "=r"(r0), "=r"(r1), "=r"(r2), "=r"(r3) : "r"(addr));
}
__device__ __forceinline__ void mma_f16(float* d, const uint32_t* a, const uint32_t* b) {
    asm volatile("mma.sync.aligned.m16n8k16.row.col.f32.f16.f16.f32 "
        "{%0,%1,%2,%3}, {%4,%5,%6,%7}, {%8,%9}, {%0,%1,%2,%3};"
        : "+f"(d[0]), "+f"(d[1]), "+f"(d[2]), "+f"(d[3])
        : "r"(a[0]), "r"(a[1]), "r"(a[2]), "r"(a[3]), "r"(b[0]), "r"(b[1]));
}

// ========== fp16 cp.async+ldmatrix+mma NT GEMM: C = A*B^T (+bias) ==========
// A [M,K] fp16 row-major; B stored [N,K] fp16 row-major. BM=128, BK=32.
template <int BN, int WM, int WN, int MT, int NT, bool OUTH>
__global__ void __launch_bounds__(256) gemm16(
    const __half* __restrict__ Ag, const __half* __restrict__ Bg,
    const float* __restrict__ biasg, void* __restrict__ Cg,
    int lda, int ldb, int ldc, int K,
    long long aZ, long long bZ, long long biasZ, long long cZ)
{
    constexpr int BM = 128;
    constexpr int RS = 40;                 // halves per smem row (32 data + 8 pad)
    constexpr int SA_H = BM * RS;
    constexpr int SB_H = BN * RS;
    constexpr int STAGE_B = (SA_H + SB_H) * 2;
    constexpr int ACH = (BM * 4) / 256;    // 16B chunks per thread for A
    constexpr int BCH = (BN * 4) / 256;

    extern __shared__ __half sh[];
    uint32_t smb = smem_u32(sh);

    const int tid = threadIdx.x, lane = tid & 31, wid = tid >> 5;
    const int wm = wid % WM, wn = wid / WM;
    const int m_base = wm * (MT * 16), n_base = wn * (NT * 8);
    const int m0 = blockIdx.y * BM, n0 = blockIdx.x * BN;

    const __half* A = Ag + (long long)blockIdx.z * aZ + (size_t)m0 * lda;
    const __half* B = Bg + (long long)blockIdx.z * bZ + (size_t)n0 * ldb;
    const float* bias = biasg ? (biasg + (long long)blockIdx.z * biasZ) : (const float*)0;

    uint32_t sOffA[ACH]; const __half* gA[ACH];
    #pragma unroll
    for (int i = 0; i < ACH; i++) {
        int u = tid + i * 256, r = u >> 2, ch = u & 3;
        sOffA[i] = (uint32_t)(r * RS + ch * 8) * 2;
        gA[i] = A + (size_t)r * lda + ch * 8;
    }
    uint32_t sOffB[BCH]; const __half* gB[BCH];
    #pragma unroll
    for (int i = 0; i < BCH; i++) {
        int u = tid + i * 256, r = u >> 2, ch = u & 3;
        sOffB[i] = (uint32_t)(r * RS + ch * 8) * 2 + SA_H * 2;
        gB[i] = B + (size_t)r * ldb + ch * 8;
    }

    const int NTILES = K >> 5;

    // prologue: stages 0,1
    {
        uint32_t base = smb;
        #pragma unroll
        for (int i = 0; i < ACH; i++) cp_async16(base + sOffA[i], gA[i]);
        #pragma unroll
        for (int i = 0; i < BCH; i++) cp_async16(base + sOffB[i], gB[i]);
    }
    CP_COMMIT();
    {
        uint32_t base = smb + STAGE_B;
        #pragma unroll
        for (int i = 0; i < ACH; i++) cp_async16(base + sOffA[i], gA[i] + 32);
        #pragma unroll
        for (int i = 0; i < BCH; i++) cp_async16(base + sOffB[i], gB[i] + 32);
    }
    CP_COMMIT();

    float acc[MT][NT][4];
    #pragma unroll
    for (int i = 0; i < MT; i++)
        #pragma unroll
        for (int j = 0; j < NT; j++)
            #pragma unroll
            for (int q = 0; q < 4; q++) acc[i][j][q] = 0.f;

    for (int kt = 0; kt < NTILES; kt++) {
        if (kt + 2 < NTILES) {
            uint32_t base = smb + ((kt + 2) % 3) * STAGE_B;
            #pragma unroll
            for (int i = 0; i < ACH; i++) cp_async16(base + sOffA[i], gA[i] + (kt + 2) * 32);
            #pragma unroll
            for (int i = 0; i < BCH; i++) cp_async16(base + sOffB[i], gB[i] + (kt + 2) * 32);
        }
        CP_COMMIT();
        CP_WAIT2();
        __syncthreads();

        uint32_t baseA = smb + (kt % 3) * STAGE_B;
        uint32_t baseB = baseA + SA_H * 2;
        #pragma unroll
        for (int ks = 0; ks < 2; ks++) {
            uint32_t af[MT][4];
            #pragma unroll
            for (int mt = 0; mt < MT; mt++) {
                int row = m_base + mt * 16 + (lane & 7) + ((lane >> 3) & 1) * 8;
                int col = ks * 16 + (lane >> 4) * 8;
                ldm4(af[mt][0], af[mt][1], af[mt][2], af[mt][3],
                     baseA + (uint32_t)(row * RS + col) * 2);
            }
            uint32_t bf[NT][2];
            #pragma unroll
            for (int np = 0; np < NT / 2; np++) {
                int row = n_base + np * 16 + (lane & 7) + ((lane >> 4) & 1) * 8;
                int col = ks * 16 + ((lane >> 3) & 1) * 8;
                uint32_t r0, r1, r2, r3;
                ldm4(r0, r1, r2, r3, baseB + (uint32_t)(row * RS + col) * 2);
                bf[2 * np][0] = r0; bf[2 * np][1] = r1;
                bf[2 * np + 1][0] = r2; bf[2 * np + 1][1] = r3;
            }
            #pragma unroll
            for (int mt = 0; mt < MT; mt++)
                #pragma unroll
                for (int nt = 0; nt < NT; nt++)
                    mma_f16(acc[mt][nt], af[mt], bf[nt]);
        }
        __syncthreads();
    }

    // epilogue
    const int g = lane >> 2, c = lane & 3;
    #pragma unroll
    for (int mt = 0; mt < MT; mt++) {
        int row = m0 + m_base + mt * 16 + g;
        #pragma unroll
        for (int nt = 0; nt < NT; nt++) {
            int col = n0 + n_base + nt * 8 + 2 * c;
            float bx = 0.f, by = 0.f;
            if (bias) { bx = bias[col]; by = bias[col + 1]; }
            float v00 = acc[mt][nt][0] + bx, v01 = acc[mt][nt][1] + by;
            float v10 = acc[mt][nt][2] + bx, v11 = acc[mt][nt][3] + by;
            if (OUTH) {
                __half* C = (__half*)Cg + (long long)blockIdx.z * cZ;
                __half2 h0 = __floats2half2_rn(v00, v01);
                __half2 h1 = __floats2half2_rn(v10, v11);
                *(__half2*)(C + (size_t)row * ldc + col) = h0;
                *(__half2*)(C + (size_t)(row + 8) * ldc + col) = h1;
            } else {
                float* C = (float*)Cg + (long long)blockIdx.z * cZ;
                *(float2*)(C + (size_t)row * ldc + col) = make_float2(v00, v01);
                *(float2*)(C + (size_t)(row + 8) * ldc + col) = make_float2(v10, v11);
            }
        }
    }
}

// ================= small prep kernels =================
__global__ void k_matvec(const float* __restrict__ W, const float* __restrict__ x,
                         const float* __restrict__ bias, float* __restrict__ y) {
    int row = blockIdx.x * 8 + (threadIdx.x >> 5);
    int lane = threadIdx.x & 31;
    const float* w = W + (size_t)row * DD;
    float acc = 0.f;
    for (int d = lane * 4; d < DD; d += 128) {
        float4 wv = *(const float4*)(w + d);
        float4 xv = *(const float4*)(x + d);
        acc += wv.x * xv.x + wv.y * xv.y + wv.z * xv.z + wv.w * xv.w;
    }
    #pragma unroll
    for (int o = 16; o; o >>= 1) acc += __shfl_xor_sync(0xffffffffu, acc, o);
    if (lane == 0) y[row] = acc + (bias ? bias[row] : 0.f);
}

__global__ void k_t_kernel(const float* __restrict__ Wk_in) {
    int idx = blockIdx.x * 256 + threadIdx.x;
    int h = idx >> 10, m = idx & 1023;
    const float* q = g_qfull + h * HDIM;
    float acc = 0.f;
    #pragma unroll 8
    for (int j = 0; j < HDIM; j++)
        acc += q[j] * Wk_in[(size_t)(h * HDIM + j) * DD + m];
    g_t[idx] = acc * 0.125f;
}

__global__ void k_r_kernel(const float* __restrict__ Wk_lin) {
    int idx = blockIdx.x * 256 + threadIdx.x;
    int h = idx >> 10, d = idx & 1023;
    const float* t = g_t + h * DD;
    float acc = 0.f;
    #pragma unroll 8
    for (int m = 0; m < DD; m++)
        acc += t[m] * Wk_lin[(size_t)m * DD + d];
    g_r[idx] = acc;
}

__global__ void k_cvt16(const float4* __restrict__ in, uint2* __restrict__ out) {
    int i = blockIdx.x * 256 + threadIdx.x;
    float4 v = in[i];
    __half2 h0 = __floats2half2_rn(v.x, v.y);
    __half2 h1 = __floats2half2_rn(v.z, v.w);
    out[i] = make_uint2(*(uint32_t*)&h0, *(uint32_t*)&h1);
}

__global__ void k_transpose16(const float* __restrict__ in, __half* __restrict__ out) {
    __shared__ float t[32][33];
    int x = blockIdx.x * 32 + threadIdx.x;
    int y = blockIdx.y * 32 + threadIdx.y;
    #pragma unroll
    for (int j = 0; j < 32; j += 8)
        t[threadIdx.y + j][threadIdx.x] = in[(size_t)(y + j) * DD + x];
    __syncthreads();
    x = blockIdx.y * 32 + threadIdx.x;
    y = blockIdx.x * 32 + threadIdx.y;
    #pragma unroll
    for (int j = 0; j < 32; j += 8)
        out[(size_t)(y + j) * DD + x] = __float2half_rn(t[threadIdx.x][threadIdx.y + j]);
}

// ============ fused scores + softmax + mixed, one CTA per (s,b) =============
#define ENT_STRIDE 1028
#define FUSED_SMEM ((16 * ENT_STRIDE + 512 + 256) * 4)

__global__ void __launch_bounds__(256) k_fused(const float* __restrict__ ent,
                                               const unsigned char* __restrict__ pm) {
    extern __shared__ float sm[];
    float* ent_s  = sm;                       // [16][1028]
    float* part_s = sm + 16 * ENT_STRIDE;     // [2][16][16]
    float* attn_t = part_s + 512;             // [e][h]
    int sb = blockIdx.x;
    int s = sb >> 5, b = sb & 31;
    int tid = threadIdx.x;

    const float* base = ent + ((size_t)s * EE * BB + b) * DD;
    #pragma unroll
    for (int i = 0; i < 16; i++) {
        int lin = tid + i * 256;
        int e = lin >> 8, cc = (lin & 255) * 4;
        float4 v = *(const float4*)(base + (size_t)e * BB * DD + cc);
        *(float4*)&ent_s[e * ENT_STRIDE + cc] = v;
    }
    __syncthreads();

    {
        int e = tid & 15, h2 = (tid >> 4) & 7, half = tid >> 7;
        int h0 = h2 * 2;
        const float* r0 = g_r + (size_t)h0 * DD + half * 512;
        const float* r1 = r0 + DD;
        const float* ev = ent_s + e * ENT_STRIDE + half * 512;
        float s0 = 0.f, s1 = 0.f;
        #pragma unroll 8
        for (int i = 0; i < 512; i += 4) {
            float4 eV = *(const float4*)(ev + i);
            float4 rA = __ldg((const float4*)(r0 + i));
            float4 rB = __ldg((const float4*)(r1 + i));
            s0 += rA.x * eV.x + rA.y * eV.y + rA.z * eV.z + rA.w * eV.w;
            s1 += rB.x * eV.x + rB.y * eV.y + rB.z * eV.z + rB.w * eV.w;
        }
        part_s[half * 256 + h0 * 16 + e] = s0;
        part_s[half * 256 + (h0 + 1) * 16 + e] = s1;
    }
    __syncthreads();

    {
        int h = tid >> 4, e = tid & 15;
        float sc = part_s[h * 16 + e] + part_s[256 + h * 16 + e];
        if (pm[(size_t)(s * EE + e) * BB + b]) sc = -INFINITY;
        float mx = sc;
        #pragma unroll
        for (int o = 8; o; o >>= 1) mx = fmaxf(mx, __shfl_xor_sync(0xffffffffu, mx, o));
        float ex = expf(sc - mx);
        float sum = ex;
        #pragma unroll
        for (int o = 8; o; o >>= 1) sum += __shfl_xor_sync(0xffffffffu, sum, o);
        attn_t[e * 16 + h] = ex / sum;
    }
    __syncthreads();

    {
        int d0 = tid * 4;
        float4 acc[16];
        #pragma unroll
        for (int h = 0; h < 16; h++) acc[h] = make_float4(0.f, 0.f, 0.f, 0.f);
        #pragma unroll
        for (int e = 0; e < 16; e++) {
            float4 v = *(const float4*)&ent_s[e * ENT_STRIDE + d0];
            float4 w0 = *(const float4*)&attn_t[e * 16 + 0];
            float4 w1 = *(const float4*)&attn_t[e * 16 + 4];
            float4 w2 = *(const float4*)&attn_t[e * 16 + 8];
            float4 w3 = *(const float4*)&attn_t[e * 16 + 12];
            acc[0].x += w0.x * v.x;  acc[0].y += w0.x * v.y;  acc[0].z += w0.x * v.z;  acc[0].w += w0.x * v.w;
            acc[1].x += w0.y * v.x;  acc[1].y += w0.y * v.y;  acc[1].z += w0.y * v.z;  acc[1].w += w0.y * v.w;
            acc[2].x += w0.z * v.x;  acc[2].y += w0.z * v.y;  acc[2].z += w0.z * v.z;  acc[2].w += w0.z * v.w;
            acc[3].x += w0.w * v.x;  acc[3].y += w0.w * v.y;  acc[3].z += w0.w * v.z;  acc[3].w += w0.w * v.w;
            acc[4].x += w1.x * v.x;  acc[4].y += w1.x * v.y;  acc[4].z += w1.x * v.z;  acc[4].w += w1.x * v.w;
            acc[5].x += w1.y * v.x;  acc[5].y += w1.y * v.y;  acc[5].z += w1.y * v.z;  acc[5].w += w1.y * v.w;
            acc[6].x += w1.z * v.x;  acc[6].y += w1.z * v.y;  acc[6].z += w1.z * v.z;  acc[6].w += w1.z * v.w;
            acc[7].x += w1.w * v.x;  acc[7].y += w1.w * v.y;  acc[7].z += w1.w * v.z;  acc[7].w += w1.w * v.w;
            acc[8].x += w2.x * v.x;  acc[8].y += w2.x * v.y;  acc[8].z += w2.x * v.z;  acc[8].w += w2.x * v.w;
            acc[9].x += w2.y * v.x;  acc[9].y += w2.y * v.y;  acc[9].z += w2.y * v.z;  acc[9].w += w2.y * v.w;
            acc[10].x += w2.z * v.x; acc[10].y += w2.z * v.y; acc[10].z += w2.z * v.z; acc[10].w += w2.z * v.w;
            acc[11].x += w2.w * v.x; acc[11].y += w2.w * v.y; acc[11].z += w2.w * v.z; acc[11].w += w2.w * v.w;
            acc[12].x += w3.x * v.x; acc[12].y += w3.x * v.y; acc[12].z += w3.x * v.z; acc[12].w += w3.x * v.w;
            acc[13].x += w3.y * v.x; acc[13].y += w3.y * v.y; acc[13].z += w3.y * v.z; acc[13].w += w3.y * v.w;
            acc[14].x += w3.z * v.x; acc[14].y += w3.z * v.y; acc[14].z += w3.z * v.z; acc[14].w += w3.z * v.w;
            acc[15].x += w3.w * v.x; acc[15].y += w3.w * v.y; acc[15].z += w3.w * v.z; acc[15].w += w3.w * v.w;
        }
        #pragma unroll
        for (int h = 0; h < 16; h++) {
            __half2 h0 = __floats2half2_rn(acc[h].x, acc[h].y);
            __half2 h1 = __floats2half2_rn(acc[h].z, acc[h].w);
            *(uint2*)&g_mixed16[((size_t)h * SB + sb) * DD + d0] =
                make_uint2(*(uint32_t*)&h0, *(uint32_t*)&h1);
        }
    }
}

// ================= launch =================
extern "C" void kernel_launch(void* const* d_in, const int* in_sizes, int n_in,
                              void* d_out, int out_size) {
    const float*         entities = (const float*)d_in[0];
    const unsigned char* pm       = (const unsigned char*)d_in[1];
    const float* query  = (const float*)d_in[3];
    const float* Wk_lin = (const float*)d_in[4];
    const float* Wv_lin = (const float*)d_in[6];
    const float* bv_lin = (const float*)d_in[7];
    const float* Wq_in  = (const float*)d_in[8];
    const float* bq_in  = (const float*)d_in[9];
    const float* Wk_in  = (const float*)d_in[10];
    const float* Wv_in  = (const float*)d_in[12];
    const float* bv_in  = (const float*)d_in[13];
    const float* Wo     = (const float*)d_in[14];
    const float* bo     = (const float*)d_in[15];
    float* out = (float*)d_out;

    float *gq, *gbcv;
    __half *gWvin16, *gWvlinT16, *gWo16, *gWcv16, *gmixed16, *gctx16;
    cudaGetSymbolAddress((void**)&gq,       g_qfull);
    cudaGetSymbolAddress((void**)&gbcv,     g_bcv);
    cudaGetSymbolAddress((void**)&gWvin16,  g_Wvin16);
    cudaGetSymbolAddress((void**)&gWvlinT16,g_WvlinT16);
    cudaGetSymbolAddress((void**)&gWo16,    g_Wo16);
    cudaGetSymbolAddress((void**)&gWcv16,   g_Wcv16);
    cudaGetSymbolAddress((void**)&gmixed16, g_mixed16);
    cudaGetSymbolAddress((void**)&gctx16,   g_ctx16);

    const int SMB128 = (128 + 128) * 40 * 2 * 3;  // 61440
    const int SMB64  = (128 + 64) * 40 * 2 * 3;   // 46080
    cudaFuncSetAttribute((const void*)gemm16<128, 2, 4, 4, 4, true>,
                         cudaFuncAttributeMaxDynamicSharedMemorySize, SMB128);
    cudaFuncSetAttribute((const void*)gemm16<128, 2, 4, 4, 4, false>,
                         cudaFuncAttributeMaxDynamicSharedMemorySize, SMB128);
    cudaFuncSetAttribute((const void*)gemm16<64, 4, 2, 2, 4, true>,
                         cudaFuncAttributeMaxDynamicSharedMemorySize, SMB64);
    cudaFuncSetAttribute(k_fused, cudaFuncAttributeMaxDynamicSharedMemorySize, FUSED_SMEM);

    // prep (fp32 score path + fp16 weight conversion)
    k_matvec<<<128, 256>>>(Wq_in, query, bq_in, gq);
    k_t_kernel<<<64, 256>>>(Wk_in);
    k_r_kernel<<<64, 256>>>(Wk_lin);
    k_matvec<<<128, 256>>>(Wv_in, bv_lin, bv_in, gbcv);
    k_cvt16<<<1024, 256>>>((const float4*)Wv_in, (uint2*)gWvin16);
    k_cvt16<<<1024, 256>>>((const float4*)Wo, (uint2*)gWo16);
    k_transpose16<<<dim3(32, 32), dim3(32, 8)>>>(Wv_lin, gWvlinT16);

    // Wcv = Wv_in @ Wv_lin (fp16 out)
    gemm16<128, 2, 4, 4, 4, true><<<dim3(8, 8, 1), 256, SMB128>>>(
        gWvin16, gWvlinT16, nullptr, gWcv16, DD, DD, DD, DD, 0, 0, 0, 0);

    // fused scores + softmax + mixed (fp16 out)
    k_fused<<<SB, 256, FUSED_SMEM>>>(entities, pm);

    // ctx_h = mixed_h @ Wcv_h^T + bcv_h (fp16 out), z = head
    gemm16<64, 4, 2, 2, 4, true><<<dim3(1, 16, HH), 256, SMB64>>>(
        gmixed16, gWcv16, gbcv, gctx16, DD, DD, DD, DD,
        (long long)SB * DD, (long long)HDIM * DD, HDIM, HDIM);

    // out = ctx @ Wo^T + bo (fp32 out)
    gemm16<128, 2, 4, 4, 4, false><<<dim3(8, 16, 1), 256, SMB128>>>(
        gctx16, gWo16, bo, out, DD, DD, DD, DD, 0, 0, 0, 0);
}